// round 7
// baseline (speedup 1.0000x reference)
#include <cuda_runtime.h>
#include <cstdint>

// ---------------------------------------------------------------------------
// Attention_layer, R6: merged KQV projection (x read once, 1 LDS.128 per
// weight matrix per c via 4s x 8d lane tile) to cut L1TEX traffic (~82% SOL
// in R5). kT/qT alias dead X region; v in registers; 2 CTAs/SM.
// ---------------------------------------------------------------------------

#define ULL unsigned long long

__device__ __forceinline__ ULL d2(float x) {
    ULL r; asm("mov.b64 %0,{%1,%1};" : "=l"(r) : "f"(x)); return r;
}
__device__ __forceinline__ void fma2(ULL& a, ULL b, ULL c) {
    asm("fma.rn.f32x2 %0,%1,%2,%0;" : "+l"(a) : "l"(b), "l"(c));
}
__device__ __forceinline__ float2 unpk(ULL a) {
    float lo, hi; asm("mov.b64 {%0,%1},%2;" : "=f"(lo), "=f"(hi) : "l"(a));
    return make_float2(lo, hi);
}
__device__ __forceinline__ float ex2(float x) {
    float r; asm("ex2.approx.f32 %0,%1;" : "=f"(r) : "f"(x)); return r;
}

// Problem constants
static constexpr int B  = 8;
static constexpr int CH = 64;
static constexpr int D  = 32;
static constexpr int H  = 64;
static constexpr int W  = 64;
static constexpr int S  = 32;
static constexpr int WT = 8;            // positions (warps) per CTA
static constexpr int HW = H * W;

static constexpr int RP  = 36;
static constexpr int UW  = 2308;        // per-warp union: X(2048) | kT(1152)+qT(1152)
static constexpr int QT_BASE = 1156;

// smem layout (floats)
static constexpr int OFF_U    = 0;                   // 8 * 2308
static constexpr int OFF_WKT  = OFF_U + WT * UW;
static constexpr int OFF_WQT  = OFF_WKT + CH * S;
static constexpr int OFF_WVT  = OFF_WQT + CH * S;
static constexpr int OFF_WOT  = OFF_WVT + CH * S;    // [s][c] 32*64
static constexpr int OFF_BK   = OFF_WOT + S * CH;
static constexpr int OFF_BQ   = OFF_BK + S;
static constexpr int OFF_BV   = OFF_BQ + S;
static constexpr int OFF_BO   = OFF_BV + S;
static constexpr int OFF_AB   = OFF_BO + CH;         // abar/om: 8 warps * 32
static constexpr int OFF_OUT  = OFF_AB + WT * S;
static constexpr int SMEM_FLOATS = OFF_OUT + CH * WT;
static constexpr size_t SMEM_BYTES = (size_t)SMEM_FLOATS * 4;   // ~107.8 KB

__global__ __launch_bounds__(256, 2)
void attn_fused_kernel(const float* __restrict__ x,
                       const float* __restrict__ Wk, const float* __restrict__ bk,
                       const float* __restrict__ Wq, const float* __restrict__ bq,
                       const float* __restrict__ Wv, const float* __restrict__ bv,
                       const float* __restrict__ Wo, const float* __restrict__ bo,
                       const float* __restrict__ factor,
                       float* __restrict__ out)
{
    extern __shared__ float sm[];
    const int tid  = threadIdx.x;
    const int blk  = blockIdx.x;
    const int b    = blk >> 9;
    const int rem  = blk & 511;
    const int h    = rem >> 3;
    const int w0   = (rem & 7) << 3;

    // ---- Stage x tile: [c][d][w0..w0+7] gmem -> smem [w][c*32+d] ----
    const float* base_in = x + (size_t)b * (CH * D) * HW + h * W + w0;
    #pragma unroll 4
    for (int it = 0; it < 32; ++it) {
        int idx = it * 256 + tid;
        int cd  = idx >> 2;
        int w2  = (idx & 3) << 1;
        float2 v = *(const float2*)(base_in + (size_t)cd * HW + w2);
        sm[OFF_U + w2 * UW + cd]       = v.x;
        sm[OFF_U + (w2 + 1) * UW + cd] = v.y;
    }

    // ---- Stage weights (transposed [c][s]) ----
    for (int i = tid; i < CH * S; i += 256) {
        int c = i >> 5, s = i & 31;
        sm[OFF_WKT + i] = Wk[s * CH + c];
        sm[OFF_WQT + i] = Wq[s * CH + c];
        sm[OFF_WVT + i] = Wv[s * CH + c];
        int s2 = i >> 6, c2 = i & 63;
        sm[OFF_WOT + i] = Wo[c2 * S + s2];
    }
    if (tid < S) {
        sm[OFF_BK + tid] = bk[tid];
        sm[OFF_BQ + tid] = bq[tid];
        sm[OFF_BV + tid] = bv[tid];
    }
    if (tid < CH) sm[OFF_BO + tid] = bo[tid];
    __syncthreads();

    const int warp = tid >> 5;
    const int lane = tid & 31;
    // scores-phase decomposition
    const int sg   = lane >> 3;   // 0..3
    const int jg   = lane & 7;    // 0..7
    // projection-phase decomposition
    const int sgrp = lane >> 2;   // 0..7 : s = sgrp*4 .. +3
    const int dgrp = lane & 3;    // 0..3 : d = dgrp*8 .. +7

    float* xw    = sm + OFF_U + warp * UW;          // X now; kT/qT later
    float* kT    = xw;
    float* qT    = xw + QT_BASE;
    float* ABARw = sm + OFF_AB + warp * S;

    // ---- x mean over d (X dies before phase F) ----
    float mx0 = 0.f, mx1 = 0.f;
    #pragma unroll
    for (int t = 0; t < 8; ++t) {
        int cb = ((t + lane) & 7) << 2;
        float4 a = *(const float4*)(xw + lane * 32 + cb);
        float4 bb = *(const float4*)(xw + (lane + 32) * 32 + cb);
        mx0 += (a.x + a.y) + (a.z + a.w);
        mx1 += (bb.x + bb.y) + (bb.z + bb.w);
    }

    // ============== Merged projections: k, q, v in one x sweep =============
    // lane computes 4 s (2 packed pairs) x 8 d for each matrix
    ULL ak[2][8], aq[2][8], av[2][8];
    {
        const ULL* bk2 = (const ULL*)(sm + OFF_BK);
        const ULL* bq2 = (const ULL*)(sm + OFF_BQ);
        const ULL* bv2 = (const ULL*)(sm + OFF_BV);
        ULL bK0 = bk2[sgrp * 2], bK1 = bk2[sgrp * 2 + 1];
        ULL bQ0 = bq2[sgrp * 2], bQ1 = bq2[sgrp * 2 + 1];
        ULL bV0 = bv2[sgrp * 2], bV1 = bv2[sgrp * 2 + 1];
        #pragma unroll
        for (int dd = 0; dd < 8; ++dd) {
            ak[0][dd] = bK0; ak[1][dd] = bK1;
            aq[0][dd] = bQ0; aq[1][dd] = bQ1;
            av[0][dd] = bV0; av[1][dd] = bV1;
        }
    }
    {
        const float* xb  = xw + dgrp * 8;
        const float* wkb = sm + OFF_WKT + sgrp * 4;
        const float* wqb = sm + OFF_WQT + sgrp * 4;
        const float* wvb = sm + OFF_WVT + sgrp * 4;
        #pragma unroll 2
        for (int c = 0; c < CH; ++c) {
            float4 x0 = *(const float4*)(xb + c * 32);
            float4 x1 = *(const float4*)(xb + c * 32 + 4);
            ulonglong2 wk2 = *(const ulonglong2*)(wkb + c * 32);
            ulonglong2 wq2 = *(const ulonglong2*)(wqb + c * 32);
            ulonglong2 wv2 = *(const ulonglong2*)(wvb + c * 32);
            float xs[8] = {x0.x, x0.y, x0.z, x0.w, x1.x, x1.y, x1.z, x1.w};
            #pragma unroll
            for (int dd = 0; dd < 8; ++dd) {
                ULL xd = d2(xs[dd]);
                fma2(ak[0][dd], wk2.x, xd); fma2(ak[1][dd], wk2.y, xd);
                fma2(aq[0][dd], wq2.x, xd); fma2(aq[1][dd], wq2.y, xd);
                fma2(av[0][dd], wv2.x, xd); fma2(av[1][dd], wv2.y, xd);
            }
        }
    }
    __syncwarp();
    // X dead -> store kT/qT transposed [d][s] over the X region (v stays in regs)
    #pragma unroll
    for (int dd = 0; dd < 8; ++dd) {
        int d = dgrp * 8 + dd;
        ulonglong2 kst; kst.x = ak[0][dd]; kst.y = ak[1][dd];
        ulonglong2 qst; qst.x = aq[0][dd]; qst.y = aq[1][dd];
        *(ulonglong2*)(kT + d * RP + sgrp * 4) = kst;
        *(ulonglong2*)(qT + d * RP + sgrp * 4) = qst;
    }
    __syncwarp();

    // ================= Phase B: scores[i][j] = sum_s k[s][i] q[s][j] =======
    ULL acc[8][4];
    #pragma unroll
    for (int ti = 0; ti < 8; ++ti)
        #pragma unroll
        for (int tj = 0; tj < 4; ++tj) acc[ti][tj] = 0ull;

    #pragma unroll 2
    for (int sq = 0; sq < 8; ++sq) {
        ulonglong2 kk[8];
        #pragma unroll
        for (int ti = 0; ti < 8; ++ti)
            kk[ti] = *(const ulonglong2*)(kT + (4 * ti + sg) * RP + sq * 4);
        ulonglong2 qq[4];
        #pragma unroll
        for (int tj = 0; tj < 4; ++tj)
            qq[tj] = *(const ulonglong2*)(qT + (8 * tj + jg) * RP + sq * 4);
        #pragma unroll
        for (int ti = 0; ti < 8; ++ti)
            #pragma unroll
            for (int tj = 0; tj < 4; ++tj) {
                fma2(acc[ti][tj], kk[ti].x, qq[tj].x);
                fma2(acc[ti][tj], kk[ti].y, qq[tj].y);
            }
    }
    float sc[8][4];
    #pragma unroll
    for (int ti = 0; ti < 8; ++ti)
        #pragma unroll
        for (int tj = 0; tj < 4; ++tj) { float2 u = unpk(acc[ti][tj]); sc[ti][tj] = u.x + u.y; }

    // ================= Phase C: softmax over i (per column j) ==============
    const float CEXP = 0.17677669529663687f * 1.44269504088896340f;
    #pragma unroll
    for (int tj = 0; tj < 4; ++tj) {
        float m = sc[0][tj];
        #pragma unroll
        for (int ti = 1; ti < 8; ++ti) m = fmaxf(m, sc[ti][tj]);
        m = fmaxf(m, __shfl_xor_sync(0xffffffffu, m, 8));
        m = fmaxf(m, __shfl_xor_sync(0xffffffffu, m, 16));
        float sum = 0.f;
        #pragma unroll
        for (int ti = 0; ti < 8; ++ti) {
            float e = ex2((sc[ti][tj] - m) * CEXP);
            sc[ti][tj] = e; sum += e;
        }
        sum += __shfl_xor_sync(0xffffffffu, sum, 8);
        sum += __shfl_xor_sync(0xffffffffu, sum, 16);
        float r = 1.0f / sum;
        #pragma unroll
        for (int ti = 0; ti < 8; ++ti) sc[ti][tj] *= r;
    }

    // ---- abar[i] = (1/32) * sum_j a[i][j] ----
    float ab[8];
    #pragma unroll
    for (int ti = 0; ti < 8; ++ti)
        ab[ti] = (sc[ti][0] + sc[ti][1]) + (sc[ti][2] + sc[ti][3]);
    #pragma unroll
    for (int ti = 0; ti < 8; ++ti) {
        ab[ti] += __shfl_xor_sync(0xffffffffu, ab[ti], 1);
        ab[ti] += __shfl_xor_sync(0xffffffffu, ab[ti], 2);
        ab[ti] += __shfl_xor_sync(0xffffffffu, ab[ti], 4);
    }
    if (jg == 0) {
        #pragma unroll
        for (int ti = 0; ti < 8; ++ti)
            ABARw[4 * ti + sg] = ab[ti] * (1.0f / 32.0f);
    }
    __syncwarp();

    // ================= Phase D': om[s] = sum_d v[s][d] * abar[d] ==========
    {
        float4 ab0 = *(const float4*)(ABARw + dgrp * 8);
        float4 ab1 = *(const float4*)(ABARw + dgrp * 8 + 4);
        __syncwarp();
        float abs_[8] = {ab0.x, ab0.y, ab0.z, ab0.w, ab1.x, ab1.y, ab1.z, ab1.w};
        ULL ao0 = 0ull, ao1 = 0ull;
        #pragma unroll
        for (int dd = 0; dd < 8; ++dd) {
            ULL a = d2(abs_[dd]);
            fma2(ao0, av[0][dd], a);
            fma2(ao1, av[1][dd], a);
        }
        float2 u0 = unpk(ao0), u1 = unpk(ao1);
        float o0 = u0.x, o1 = u0.y, o2 = u1.x, o3 = u1.y;
        o0 += __shfl_xor_sync(0xffffffffu, o0, 1); o0 += __shfl_xor_sync(0xffffffffu, o0, 2);
        o1 += __shfl_xor_sync(0xffffffffu, o1, 1); o1 += __shfl_xor_sync(0xffffffffu, o1, 2);
        o2 += __shfl_xor_sync(0xffffffffu, o2, 1); o2 += __shfl_xor_sync(0xffffffffu, o2, 2);
        o3 += __shfl_xor_sync(0xffffffffu, o3, 1); o3 += __shfl_xor_sync(0xffffffffu, o3, 2);
        if (dgrp == 0) {
            float4 st; st.x = o0; st.y = o1; st.z = o2; st.w = o3;
            *(float4*)(ABARw + sgrp * 4) = st;    // om overwrites abar
        }
    }
    __syncwarp();

    // ================= Phase F: out = mean_d(x) + f*(Wo*om + bo) ===========
    const float fact = factor[0];
    float4 om4[8];
    #pragma unroll
    for (int t = 0; t < 8; ++t) om4[t] = *(const float4*)(ABARw + t * 4);
    float ac0 = 0.f, ac1 = 0.f;
    #pragma unroll
    for (int t = 0; t < 8; ++t) {
        const float* wo = sm + OFF_WOT + (4 * t) * CH + lane;
        ac0 += wo[0]        * om4[t].x;  ac1 += wo[32]         * om4[t].x;
        ac0 += wo[64]       * om4[t].y;  ac1 += wo[96]         * om4[t].y;
        ac0 += wo[128]      * om4[t].z;  ac1 += wo[160]        * om4[t].z;
        ac0 += wo[192]      * om4[t].w;  ac1 += wo[224]        * om4[t].w;
    }
    float r0 = mx0 * (1.0f / 32.0f) + fact * (ac0 + sm[OFF_BO + lane]);
    float r1 = mx1 * (1.0f / 32.0f) + fact * (ac1 + sm[OFF_BO + lane + 32]);
    sm[OFF_OUT + lane * 8 + warp]        = r0;
    sm[OFF_OUT + (lane + 32) * 8 + warp] = r1;

    __syncthreads();
    // coalesced output: out[b][c][h][w0..w0+7]
    for (int e = tid; e < CH * WT; e += 256) {
        int c = e >> 3, wl = e & 7;
        out[(((size_t)b * CH + c) * H + h) * W + w0 + wl] = sm[OFF_OUT + e];
    }
}

extern "C" void kernel_launch(void* const* d_in, const int* in_sizes, int n_in,
                              void* d_out, int out_size)
{
    (void)in_sizes; (void)n_in; (void)out_size;
    const float* x      = (const float*)d_in[0];
    const float* Wk     = (const float*)d_in[1];
    const float* bk     = (const float*)d_in[2];
    const float* Wq     = (const float*)d_in[3];
    const float* bq     = (const float*)d_in[4];
    const float* Wv     = (const float*)d_in[5];
    const float* bv     = (const float*)d_in[6];
    const float* Wo     = (const float*)d_in[7];
    const float* bo     = (const float*)d_in[8];
    const float* factor = (const float*)d_in[9];
    float* out = (float*)d_out;

    cudaFuncSetAttribute(attn_fused_kernel,
                         cudaFuncAttributeMaxDynamicSharedMemorySize,
                         (int)SMEM_BYTES);
    dim3 grid(B * H * (W / WT));   // 4096
    dim3 block(256);
    attn_fused_kernel<<<grid, block, SMEM_BYTES>>>(
        x, Wk, bk, Wq, bq, Wv, bv, Wo, bo, factor, out);
}

// round 9
// speedup vs baseline: 1.8657x; 1.8657x over previous
#include <cuda_runtime.h>
#include <cuda_fp16.h>
#include <cstdint>

// ---------------------------------------------------------------------------
// Attention_layer, R8 (= R7 with compile fix): cut LDS pressure.
//  - projections retiled 4s x 8d: 1 LDS.128 per weight matrix per c
//  - kT/qT stored fp16 over dead X region; phase B = HFMA2, fp16 accum
//  - v stays in fp32 registers through B; softmax/D'/F fp32
//  - 2 CTAs/SM, ~100 KB smem
// ---------------------------------------------------------------------------

#define ULL unsigned long long

__device__ __forceinline__ ULL d2(float x) {
    ULL r; asm("mov.b64 %0,{%1,%1};" : "=l"(r) : "f"(x)); return r;
}
__device__ __forceinline__ void fma2(ULL& a, ULL b, ULL c) {
    asm("fma.rn.f32x2 %0,%1,%2,%0;" : "+l"(a) : "l"(b), "l"(c));
}
__device__ __forceinline__ float2 unpk(ULL a) {
    float lo, hi; asm("mov.b64 {%0,%1},%2;" : "=f"(lo), "=f"(hi) : "l"(a));
    return make_float2(lo, hi);
}
__device__ __forceinline__ float ex2(float x) {
    float r; asm("ex2.approx.f32 %0,%1;" : "=f"(r) : "f"(x)); return r;
}

// Problem constants
static constexpr int B  = 8;
static constexpr int CH = 64;
static constexpr int D  = 32;
static constexpr int H  = 64;
static constexpr int W  = 64;
static constexpr int S  = 32;
static constexpr int WT = 8;            // positions (warps) per CTA
static constexpr int HW = H * W;

static constexpr int RPH = 40;          // fp16 row stride (halves): 32 + 8 pad
static constexpr int UW  = 2052;        // per-warp union (floats): X(2048) | kT+qT fp16 (1280 f-eq)
static constexpr int QT_H = 1280;       // qT offset in halves (kT = 32*40 = 1280 halves)

// smem layout (floats)
static constexpr int OFF_U    = 0;                   // 8 * 2052
static constexpr int OFF_WKT  = OFF_U + WT * UW;
static constexpr int OFF_WQT  = OFF_WKT + CH * S;
static constexpr int OFF_WVT  = OFF_WQT + CH * S;
static constexpr int OFF_WOT  = OFF_WVT + CH * S;    // [s][c] 32*64
static constexpr int OFF_BK   = OFF_WOT + S * CH;
static constexpr int OFF_BQ   = OFF_BK + S;
static constexpr int OFF_BV   = OFF_BQ + S;
static constexpr int OFF_BO   = OFF_BV + S;
static constexpr int OFF_AB   = OFF_BO + CH;         // abar/om: 8 warps * 32
static constexpr int OFF_OUT  = OFF_AB + WT * S;
static constexpr int SMEM_FLOATS = OFF_OUT + CH * WT;
static constexpr size_t SMEM_BYTES = (size_t)SMEM_FLOATS * 4;   // ~99.8 KB

__global__ __launch_bounds__(256, 2)
void attn_fused_kernel(const float* __restrict__ x,
                       const float* __restrict__ Wk, const float* __restrict__ bk,
                       const float* __restrict__ Wq, const float* __restrict__ bq,
                       const float* __restrict__ Wv, const float* __restrict__ bv,
                       const float* __restrict__ Wo, const float* __restrict__ bo,
                       const float* __restrict__ factor,
                       float* __restrict__ out)
{
    extern __shared__ float sm[];
    const int tid  = threadIdx.x;
    const int blk  = blockIdx.x;
    const int b    = blk >> 9;
    const int rem  = blk & 511;
    const int h    = rem >> 3;
    const int w0   = (rem & 7) << 3;

    // ---- Stage x tile: [c][d][w0..w0+7] gmem -> smem [w][c*32+d] ----
    const float* base_in = x + (size_t)b * (CH * D) * HW + h * W + w0;
    #pragma unroll 4
    for (int it = 0; it < 32; ++it) {
        int idx = it * 256 + tid;
        int cd  = idx >> 2;
        int w2  = (idx & 3) << 1;
        float2 v = *(const float2*)(base_in + (size_t)cd * HW + w2);
        sm[OFF_U + w2 * UW + cd]       = v.x;
        sm[OFF_U + (w2 + 1) * UW + cd] = v.y;
    }

    // ---- Stage weights (transposed [c][s]) ----
    for (int i = tid; i < CH * S; i += 256) {
        int c = i >> 5, s = i & 31;
        sm[OFF_WKT + i] = Wk[s * CH + c];
        sm[OFF_WQT + i] = Wq[s * CH + c];
        sm[OFF_WVT + i] = Wv[s * CH + c];
        int s2 = i >> 6, c2 = i & 63;
        sm[OFF_WOT + i] = Wo[c2 * S + s2];
    }
    if (tid < S) {
        sm[OFF_BK + tid] = bk[tid];
        sm[OFF_BQ + tid] = bq[tid];
        sm[OFF_BV + tid] = bv[tid];
    }
    if (tid < CH) sm[OFF_BO + tid] = bo[tid];
    __syncthreads();

    const int warp = tid >> 5;
    const int lane = tid & 31;
    // scores-phase decomposition
    const int sg   = lane >> 3;   // 0..3
    const int jg   = lane & 7;    // 0..7
    // projection-phase decomposition
    const int sgrp = lane >> 2;   // 0..7 : s = sgrp*4 .. +3
    const int dgrp = lane & 3;    // 0..3 : d = dgrp*8 .. +7

    float*  xw    = sm + OFF_U + warp * UW;          // X now; kT/qT fp16 later
    __half* kTh   = (__half*)xw;                     // 1280 halves
    __half* qTh   = (__half*)xw + QT_H;              // 1280 halves
    float*  ABARw = sm + OFF_AB + warp * S;

    // ---- x mean over d (X dies before phase F) ----
    float mx0 = 0.f, mx1 = 0.f;
    #pragma unroll
    for (int t = 0; t < 8; ++t) {
        int cb = ((t + lane) & 7) << 2;
        float4 a  = *(const float4*)(xw + lane * 32 + cb);
        float4 bb = *(const float4*)(xw + (lane + 32) * 32 + cb);
        mx0 += (a.x + a.y) + (a.z + a.w);
        mx1 += (bb.x + bb.y) + (bb.z + bb.w);
    }

    // ================= Phase V: v projection (stays in regs) ===============
    // lane tile: 4 s (2 packed pairs) x 8 d
    ULL av[2][8];
    {
        const ULL* bv2 = (const ULL*)(sm + OFF_BV);
        ULL bV0 = bv2[sgrp * 2], bV1 = bv2[sgrp * 2 + 1];
        #pragma unroll
        for (int dd = 0; dd < 8; ++dd) { av[0][dd] = bV0; av[1][dd] = bV1; }

        const float* xb  = xw + dgrp * 8;
        const float* wvb = sm + OFF_WVT + sgrp * 4;
        #pragma unroll 4
        for (int c = 0; c < CH; ++c) {
            float4 x0 = *(const float4*)(xb + c * 32);
            float4 x1 = *(const float4*)(xb + c * 32 + 4);
            ulonglong2 wv2 = *(const ulonglong2*)(wvb + c * 32);
            float xs[8] = {x0.x, x0.y, x0.z, x0.w, x1.x, x1.y, x1.z, x1.w};
            #pragma unroll
            for (int dd = 0; dd < 8; ++dd) {
                ULL xd = d2(xs[dd]);
                fma2(av[0][dd], wv2.x, xd); fma2(av[1][dd], wv2.y, xd);
            }
        }
    }

    // ================= Phase KQ: k and q projections =======================
    ULL ak[2][8], aq[2][8];
    {
        const ULL* bk2 = (const ULL*)(sm + OFF_BK);
        const ULL* bq2 = (const ULL*)(sm + OFF_BQ);
        ULL bK0 = bk2[sgrp * 2], bK1 = bk2[sgrp * 2 + 1];
        ULL bQ0 = bq2[sgrp * 2], bQ1 = bq2[sgrp * 2 + 1];
        #pragma unroll
        for (int dd = 0; dd < 8; ++dd) {
            ak[0][dd] = bK0; ak[1][dd] = bK1;
            aq[0][dd] = bQ0; aq[1][dd] = bQ1;
        }
        const float* xb  = xw + dgrp * 8;
        const float* wkb = sm + OFF_WKT + sgrp * 4;
        const float* wqb = sm + OFF_WQT + sgrp * 4;
        #pragma unroll 2
        for (int c = 0; c < CH; ++c) {
            float4 x0 = *(const float4*)(xb + c * 32);
            float4 x1 = *(const float4*)(xb + c * 32 + 4);
            ulonglong2 wk2 = *(const ulonglong2*)(wkb + c * 32);
            ulonglong2 wq2 = *(const ulonglong2*)(wqb + c * 32);
            float xs[8] = {x0.x, x0.y, x0.z, x0.w, x1.x, x1.y, x1.z, x1.w};
            #pragma unroll
            for (int dd = 0; dd < 8; ++dd) {
                ULL xd = d2(xs[dd]);
                fma2(ak[0][dd], wk2.x, xd); fma2(ak[1][dd], wk2.y, xd);
                fma2(aq[0][dd], wq2.x, xd); fma2(aq[1][dd], wq2.y, xd);
            }
        }
    }
    __syncwarp();
    // X dead -> store kT/qT as fp16 [d][s] (row stride RPH halves)
    #pragma unroll
    for (int dd = 0; dd < 8; ++dd) {
        int d = dgrp * 8 + dd;
        float2 k0 = unpk(ak[0][dd]), k1 = unpk(ak[1][dd]);
        float2 q0 = unpk(aq[0][dd]), q1 = unpk(aq[1][dd]);
        __half2 kh0 = __floats2half2_rn(k0.x, k0.y);
        __half2 kh1 = __floats2half2_rn(k1.x, k1.y);
        __half2 qh0 = __floats2half2_rn(q0.x, q0.y);
        __half2 qh1 = __floats2half2_rn(q1.x, q1.y);
        *(__half2*)(kTh + d * RPH + sgrp * 4)     = kh0;
        *(__half2*)(kTh + d * RPH + sgrp * 4 + 2) = kh1;
        *(__half2*)(qTh + d * RPH + sgrp * 4)     = qh0;
        *(__half2*)(qTh + d * RPH + sgrp * 4 + 2) = qh1;
    }
    __syncwarp();

    // ================= Phase B: scores[i][j] = sum_s k[s][i] q[s][j] =======
    // fp16 HFMA2, accum packed over (s even, s odd) pairs; fold at the end.
    // i = 4*ti + sg, j = 8*tj + jg
    __half2 acc[8][4];
    {
        __half2 z = __float2half2_rn(0.f);
        #pragma unroll
        for (int ti = 0; ti < 8; ++ti)
            #pragma unroll
            for (int tj = 0; tj < 4; ++tj) acc[ti][tj] = z;
    }
    #pragma unroll
    for (int ch = 0; ch < 4; ++ch) {
        uint4 qqr[4];
        #pragma unroll
        for (int tj = 0; tj < 4; ++tj)
            qqr[tj] = *(const uint4*)(qTh + (8 * tj + jg) * RPH + ch * 8);
        #pragma unroll
        for (int ti = 0; ti < 8; ++ti) {
            uint4 kkr = *(const uint4*)(kTh + (4 * ti + sg) * RPH + ch * 8);
            const __half2* kh = (const __half2*)&kkr;
            #pragma unroll
            for (int tj = 0; tj < 4; ++tj) {
                const __half2* qh = (const __half2*)&qqr[tj];
                acc[ti][tj] = __hfma2(kh[0], qh[0], acc[ti][tj]);
                acc[ti][tj] = __hfma2(kh[1], qh[1], acc[ti][tj]);
                acc[ti][tj] = __hfma2(kh[2], qh[2], acc[ti][tj]);
                acc[ti][tj] = __hfma2(kh[3], qh[3], acc[ti][tj]);
            }
        }
    }
    float sc[8][4];
    #pragma unroll
    for (int ti = 0; ti < 8; ++ti)
        #pragma unroll
        for (int tj = 0; tj < 4; ++tj)
            sc[ti][tj] = __low2float(acc[ti][tj]) + __high2float(acc[ti][tj]);

    // ================= Phase C: softmax over i (per column j), fp32 ========
    const float CEXP = 0.17677669529663687f * 1.44269504088896340f;
    #pragma unroll
    for (int tj = 0; tj < 4; ++tj) {
        float m = sc[0][tj];
        #pragma unroll
        for (int ti = 1; ti < 8; ++ti) m = fmaxf(m, sc[ti][tj]);
        m = fmaxf(m, __shfl_xor_sync(0xffffffffu, m, 8));
        m = fmaxf(m, __shfl_xor_sync(0xffffffffu, m, 16));
        float sum = 0.f;
        #pragma unroll
        for (int ti = 0; ti < 8; ++ti) {
            float e = ex2((sc[ti][tj] - m) * CEXP);
            sc[ti][tj] = e; sum += e;
        }
        sum += __shfl_xor_sync(0xffffffffu, sum, 8);
        sum += __shfl_xor_sync(0xffffffffu, sum, 16);
        float r = 1.0f / sum;
        #pragma unroll
        for (int ti = 0; ti < 8; ++ti) sc[ti][tj] *= r;
    }

    // ---- abar[i] = (1/32) * sum_j a[i][j] ----
    float ab[8];
    #pragma unroll
    for (int ti = 0; ti < 8; ++ti)
        ab[ti] = (sc[ti][0] + sc[ti][1]) + (sc[ti][2] + sc[ti][3]);
    #pragma unroll
    for (int ti = 0; ti < 8; ++ti) {
        ab[ti] += __shfl_xor_sync(0xffffffffu, ab[ti], 1);
        ab[ti] += __shfl_xor_sync(0xffffffffu, ab[ti], 2);
        ab[ti] += __shfl_xor_sync(0xffffffffu, ab[ti], 4);
    }
    if (jg == 0) {
        #pragma unroll
        for (int ti = 0; ti < 8; ++ti)
            ABARw[4 * ti + sg] = ab[ti] * (1.0f / 32.0f);
    }
    __syncwarp();

    // ================= Phase D': om[s] = sum_d v[s][d] * abar[d] (fp32) ====
    {
        float4 ab0 = *(const float4*)(ABARw + dgrp * 8);
        float4 ab1 = *(const float4*)(ABARw + dgrp * 8 + 4);
        __syncwarp();
        float abs_[8] = {ab0.x, ab0.y, ab0.z, ab0.w, ab1.x, ab1.y, ab1.z, ab1.w};
        ULL ao0 = 0ull, ao1 = 0ull;
        #pragma unroll
        for (int dd = 0; dd < 8; ++dd) {
            ULL a = d2(abs_[dd]);
            fma2(ao0, av[0][dd], a);
            fma2(ao1, av[1][dd], a);
        }
        float2 u0 = unpk(ao0), u1 = unpk(ao1);
        float o0 = u0.x, o1 = u0.y, o2 = u1.x, o3 = u1.y;
        o0 += __shfl_xor_sync(0xffffffffu, o0, 1); o0 += __shfl_xor_sync(0xffffffffu, o0, 2);
        o1 += __shfl_xor_sync(0xffffffffu, o1, 1); o1 += __shfl_xor_sync(0xffffffffu, o1, 2);
        o2 += __shfl_xor_sync(0xffffffffu, o2, 1); o2 += __shfl_xor_sync(0xffffffffu, o2, 2);
        o3 += __shfl_xor_sync(0xffffffffu, o3, 1); o3 += __shfl_xor_sync(0xffffffffu, o3, 2);
        if (dgrp == 0) {
            float4 st; st.x = o0; st.y = o1; st.z = o2; st.w = o3;
            *(float4*)(ABARw + sgrp * 4) = st;    // om overwrites abar
        }
    }
    __syncwarp();

    // ================= Phase F: out = mean_d(x) + f*(Wo*om + bo) ===========
    const float fact = factor[0];
    float4 om4[8];
    #pragma unroll
    for (int t = 0; t < 8; ++t) om4[t] = *(const float4*)(ABARw + t * 4);
    float ac0 = 0.f, ac1 = 0.f;
    #pragma unroll
    for (int t = 0; t < 8; ++t) {
        const float* wo = sm + OFF_WOT + (4 * t) * CH + lane;
        ac0 += wo[0]   * om4[t].x;  ac1 += wo[32]  * om4[t].x;
        ac0 += wo[64]  * om4[t].y;  ac1 += wo[96]  * om4[t].y;
        ac0 += wo[128] * om4[t].z;  ac1 += wo[160] * om4[t].z;
        ac0 += wo[192] * om4[t].w;  ac1 += wo[224] * om4[t].w;
    }
    float r0 = mx0 * (1.0f / 32.0f) + fact * (ac0 + sm[OFF_BO + lane]);
    float r1 = mx1 * (1.0f / 32.0f) + fact * (ac1 + sm[OFF_BO + lane + 32]);
    sm[OFF_OUT + lane * 8 + warp]        = r0;
    sm[OFF_OUT + (lane + 32) * 8 + warp] = r1;

    __syncthreads();
    // coalesced output: out[b][c][h][w0..w0+7]
    for (int e = tid; e < CH * WT; e += 256) {
        int c = e >> 3, wl = e & 7;
        out[(((size_t)b * CH + c) * H + h) * W + w0 + wl] = sm[OFF_OUT + e];
    }
}

extern "C" void kernel_launch(void* const* d_in, const int* in_sizes, int n_in,
                              void* d_out, int out_size)
{
    (void)in_sizes; (void)n_in; (void)out_size;
    const float* x      = (const float*)d_in[0];
    const float* Wk     = (const float*)d_in[1];
    const float* bk     = (const float*)d_in[2];
    const float* Wq     = (const float*)d_in[3];
    const float* bq     = (const float*)d_in[4];
    const float* Wv     = (const float*)d_in[5];
    const float* bv     = (const float*)d_in[6];
    const float* Wo     = (const float*)d_in[7];
    const float* bo     = (const float*)d_in[8];
    const float* factor = (const float*)d_in[9];
    float* out = (float*)d_out;

    cudaFuncSetAttribute(attn_fused_kernel,
                         cudaFuncAttributeMaxDynamicSharedMemorySize,
                         (int)SMEM_BYTES);
    dim3 grid(B * H * (W / WT));   // 4096
    dim3 block(256);
    attn_fused_kernel<<<grid, block, SMEM_BYTES>>>(
        x, Wk, bk, Wq, bq, Wv, bv, Wo, bo, factor, out);
}

// round 10
// speedup vs baseline: 2.4167x; 1.2953x over previous
#include <cuda_runtime.h>
#include <cuda_fp16.h>
#include <cstdint>

// ---------------------------------------------------------------------------
// Attention_layer, R9: fp16 datapath for projections (merged single x-sweep,
// HFMA2, s-pair packed accum), x staged as dup-fp16 with fp32 mean computed
// during staging. kT/qT fp16 over dead x region; v in fp16 regs; B=HFMA2;
// softmax/D-reduce/F in fp32. 2 CTAs/SM, ~90 KB smem.
// ---------------------------------------------------------------------------

__device__ __forceinline__ float ex2(float x) {
    float r; asm("ex2.approx.f32 %0,%1;" : "=f"(r) : "f"(x)); return r;
}

// Problem constants
static constexpr int B  = 8;
static constexpr int CH = 64;
static constexpr int D  = 32;
static constexpr int H  = 64;
static constexpr int W  = 64;
static constexpr int S  = 32;
static constexpr int WT = 8;            // positions (warps) per CTA
static constexpr int HW = H * W;

static constexpr int RPH  = 40;         // kqT row stride in halves (32 + 8 pad)
static constexpr int QT_H = 1280;       // qT offset in halves (kT = 32*40)
static constexpr int UW   = 2052;       // per-warp union (floats): xh2(2048) | kqT(1280)

// smem layout (floats)
static constexpr int OFF_U    = 0;                    // 8 * 2052 = 16416
static constexpr int OFF_WKH  = OFF_U + WT * UW;      // 16416 (fp16 [c][s], 1024 fl)
static constexpr int OFF_WQH  = OFF_WKH + 1024;       // 17440
static constexpr int OFF_WVH  = OFF_WQH + 1024;       // 18464
static constexpr int OFF_WOT  = OFF_WVH + 1024;       // 19488 fp32 [s][c] 2048
static constexpr int OFF_BH   = OFF_WOT + S * CH;     // 21536 fp16 biases (96 halves)
static constexpr int OFF_BO   = OFF_BH + 48;          // 21584
static constexpr int OFF_MX   = OFF_BO + CH;          // 21648 x-mean [w][c] 512
static constexpr int OFF_AB   = OFF_MX + WT * CH;     // 22160 abar/om 8*32
static constexpr int OFF_OUT  = OFF_AB + WT * S;      // 22416
static constexpr int SMEM_FLOATS = OFF_OUT + CH * WT; // 22928
static constexpr size_t SMEM_BYTES = (size_t)SMEM_FLOATS * 4;  // ~89.6 KB

__global__ __launch_bounds__(256, 2)
void attn_fused_kernel(const float* __restrict__ x,
                       const float* __restrict__ Wk, const float* __restrict__ bk,
                       const float* __restrict__ Wq, const float* __restrict__ bq,
                       const float* __restrict__ Wv, const float* __restrict__ bv,
                       const float* __restrict__ Wo, const float* __restrict__ bo,
                       const float* __restrict__ factor,
                       float* __restrict__ out)
{
    extern __shared__ float sm[];
    const int tid  = threadIdx.x;
    const int blk  = blockIdx.x;
    const int b    = blk >> 9;
    const int rem  = blk & 511;
    const int h    = rem >> 3;
    const int w0   = (rem & 7) << 3;

    // ---- Stage x: thread = (c, w-pair). fp32 mean accumulated here; x
    //      written to smem as dup-packed fp16: xh2[c][d] = (x,x) ----
    {
        const int c  = tid >> 2;          // 0..63
        const int wp = (tid & 3) << 1;    // 0,2,4,6
        const float* bi = x + ((size_t)b * CH * D + (size_t)c * D) * HW + h * W + w0 + wp;
        __half2* xhA = (__half2*)(sm + OFF_U + (size_t)wp * UW);
        __half2* xhB = (__half2*)(sm + OFF_U + (size_t)(wp + 1) * UW);
        float msA = 0.f, msB = 0.f;
        #pragma unroll 8
        for (int d = 0; d < D; ++d) {
            float2 v = *(const float2*)(bi + (size_t)d * HW);
            msA += v.x; msB += v.y;
            xhA[c * 32 + d] = __float2half2_rn(v.x);
            xhB[c * 32 + d] = __float2half2_rn(v.y);
        }
        sm[OFF_MX + wp * CH + c]       = msA;
        sm[OFF_MX + (wp + 1) * CH + c] = msB;
    }

    // ---- Stage weights: Wk/Wq/Wv fp16 [c][s] (s-pairs packed) ----
    {
        __half2* wkh = (__half2*)(sm + OFF_WKH);
        __half2* wqh = (__half2*)(sm + OFF_WQH);
        __half2* wvh = (__half2*)(sm + OFF_WVH);
        for (int i = tid; i < 1024; i += 256) {
            int c = i >> 4, sp = i & 15, s2 = sp << 1;
            wkh[c * 16 + sp] = __floats2half2_rn(Wk[s2 * CH + c], Wk[(s2 + 1) * CH + c]);
            wqh[c * 16 + sp] = __floats2half2_rn(Wq[s2 * CH + c], Wq[(s2 + 1) * CH + c]);
            wvh[c * 16 + sp] = __floats2half2_rn(Wv[s2 * CH + c], Wv[(s2 + 1) * CH + c]);
        }
    }
    // Wo fp32 [s][c]
    for (int i = tid; i < CH * S; i += 256) {
        int s2 = i >> 6, c2 = i & 63;
        sm[OFF_WOT + i] = Wo[c2 * S + s2];
    }
    // biases fp16 (pairs)
    if (tid < 48) {
        int m = tid >> 4, t = tid & 15;
        const float* bsrc = (m == 0) ? bk : ((m == 1) ? bq : bv);
        ((__half2*)(sm + OFF_BH))[m * 16 + t] = __floats2half2_rn(bsrc[2 * t], bsrc[2 * t + 1]);
    }
    if (tid < CH) sm[OFF_BO + tid] = bo[tid];
    __syncthreads();

    const int warp = tid >> 5;
    const int lane = tid & 31;
    // scores-phase decomposition
    const int sg   = lane >> 3;   // 0..3
    const int jg   = lane & 7;    // 0..7
    // projection-phase decomposition
    const int sgrp = lane >> 2;   // 0..7 : s = sgrp*4 .. +3
    const int dgrp = lane & 3;    // 0..3 : d = dgrp*8 .. +7

    const __half* xh  = (const __half*)(sm + OFF_U + warp * UW);   // dup half2 [c][d]
    __half* kTh = (__half*)(sm + OFF_U + warp * UW);               // aliases xh2 (dead)
    __half* qTh = kTh + QT_H;
    float*  ABARw = sm + OFF_AB + warp * S;

    // ============== Merged projections k,q,v: one sweep over c =============
    // accum: half2 packed over s-pair; lane tile 4s x 8d
    __half2 acK[2][8], acQ[2][8], acV[2][8];
    {
        const __half* bh = (const __half*)(sm + OFF_BH);
        uint2 bkp = *(const uint2*)(bh + sgrp * 4);
        uint2 bqp = *(const uint2*)(bh + 32 + sgrp * 4);
        uint2 bvp = *(const uint2*)(bh + 64 + sgrp * 4);
        __half2 bk0 = *(__half2*)&bkp.x, bk1 = *(__half2*)&bkp.y;
        __half2 bq0 = *(__half2*)&bqp.x, bq1 = *(__half2*)&bqp.y;
        __half2 bv0 = *(__half2*)&bvp.x, bv1 = *(__half2*)&bvp.y;
        #pragma unroll
        for (int dd = 0; dd < 8; ++dd) {
            acK[0][dd] = bk0; acK[1][dd] = bk1;
            acQ[0][dd] = bq0; acQ[1][dd] = bq1;
            acV[0][dd] = bv0; acV[1][dd] = bv1;
        }
    }
    {
        const __half* wkh = (const __half*)(sm + OFF_WKH);
        const __half* wqh = (const __half*)(sm + OFF_WQH);
        const __half* wvh = (const __half*)(sm + OFF_WVH);
        #pragma unroll 4
        for (int c = 0; c < CH; ++c) {
            // 8 dup'd x values for this lane's d-block (2 x LDS.128)
            uint4 xr0 = *(const uint4*)(xh + c * 64 + dgrp * 16);
            uint4 xr1 = *(const uint4*)(xh + c * 64 + dgrp * 16 + 8);
            // 4 s-values per matrix (1 x LDS.64 each)
            uint2 wkr = *(const uint2*)(wkh + c * 32 + sgrp * 4);
            uint2 wqr = *(const uint2*)(wqh + c * 32 + sgrp * 4);
            uint2 wvr = *(const uint2*)(wvh + c * 32 + sgrp * 4);
            __half2 wk0 = *(__half2*)&wkr.x, wk1 = *(__half2*)&wkr.y;
            __half2 wq0 = *(__half2*)&wqr.x, wq1 = *(__half2*)&wqr.y;
            __half2 wv0 = *(__half2*)&wvr.x, wv1 = *(__half2*)&wvr.y;
            const __half2* xa = (const __half2*)&xr0;
            const __half2* xb = (const __half2*)&xr1;
            #pragma unroll
            for (int i = 0; i < 4; ++i) {
                __half2 xd = xa[i];
                acK[0][i] = __hfma2(wk0, xd, acK[0][i]);
                acK[1][i] = __hfma2(wk1, xd, acK[1][i]);
                acQ[0][i] = __hfma2(wq0, xd, acQ[0][i]);
                acQ[1][i] = __hfma2(wq1, xd, acQ[1][i]);
                acV[0][i] = __hfma2(wv0, xd, acV[0][i]);
                acV[1][i] = __hfma2(wv1, xd, acV[1][i]);
            }
            #pragma unroll
            for (int i = 0; i < 4; ++i) {
                __half2 xd = xb[i];
                acK[0][i + 4] = __hfma2(wk0, xd, acK[0][i + 4]);
                acK[1][i + 4] = __hfma2(wk1, xd, acK[1][i + 4]);
                acQ[0][i + 4] = __hfma2(wq0, xd, acQ[0][i + 4]);
                acQ[1][i + 4] = __hfma2(wq1, xd, acQ[1][i + 4]);
                acV[0][i + 4] = __hfma2(wv0, xd, acV[0][i + 4]);
                acV[1][i + 4] = __hfma2(wv1, xd, acV[1][i + 4]);
            }
        }
    }
    __syncwarp();
    // xh2 dead -> store kT/qT [d][s] fp16 (s-contiguous, matches phase B)
    #pragma unroll
    for (int dd = 0; dd < 8; ++dd) {
        int d = dgrp * 8 + dd;
        uint2 kst; kst.x = *(unsigned*)&acK[0][dd]; kst.y = *(unsigned*)&acK[1][dd];
        uint2 qst; qst.x = *(unsigned*)&acQ[0][dd]; qst.y = *(unsigned*)&acQ[1][dd];
        *(uint2*)(kTh + d * RPH + sgrp * 4) = kst;
        *(uint2*)(qTh + d * RPH + sgrp * 4) = qst;
    }
    __syncwarp();

    // ================= Phase B: scores[i][j] = sum_s k[s][i] q[s][j] =======
    // i = 4*ti + sg, j = 8*tj + jg ; fp16 HFMA2, accum packed over s-pairs
    __half2 acc[8][4];
    {
        __half2 z = __float2half2_rn(0.f);
        #pragma unroll
        for (int ti = 0; ti < 8; ++ti)
            #pragma unroll
            for (int tj = 0; tj < 4; ++tj) acc[ti][tj] = z;
    }
    #pragma unroll
    for (int ch = 0; ch < 4; ++ch) {
        uint4 qqr[4];
        #pragma unroll
        for (int tj = 0; tj < 4; ++tj)
            qqr[tj] = *(const uint4*)(qTh + (8 * tj + jg) * RPH + ch * 8);
        #pragma unroll
        for (int ti = 0; ti < 8; ++ti) {
            uint4 kkr = *(const uint4*)(kTh + (4 * ti + sg) * RPH + ch * 8);
            const __half2* kh = (const __half2*)&kkr;
            #pragma unroll
            for (int tj = 0; tj < 4; ++tj) {
                const __half2* qh = (const __half2*)&qqr[tj];
                acc[ti][tj] = __hfma2(kh[0], qh[0], acc[ti][tj]);
                acc[ti][tj] = __hfma2(kh[1], qh[1], acc[ti][tj]);
                acc[ti][tj] = __hfma2(kh[2], qh[2], acc[ti][tj]);
                acc[ti][tj] = __hfma2(kh[3], qh[3], acc[ti][tj]);
            }
        }
    }
    float sc[8][4];
    #pragma unroll
    for (int ti = 0; ti < 8; ++ti)
        #pragma unroll
        for (int tj = 0; tj < 4; ++tj)
            sc[ti][tj] = __low2float(acc[ti][tj]) + __high2float(acc[ti][tj]);

    // ================= Phase C: softmax over i (per column j), fp32 ========
    const float CEXP = 0.17677669529663687f * 1.44269504088896340f;
    #pragma unroll
    for (int tj = 0; tj < 4; ++tj) {
        float m = sc[0][tj];
        #pragma unroll
        for (int ti = 1; ti < 8; ++ti) m = fmaxf(m, sc[ti][tj]);
        m = fmaxf(m, __shfl_xor_sync(0xffffffffu, m, 8));
        m = fmaxf(m, __shfl_xor_sync(0xffffffffu, m, 16));
        float sum = 0.f;
        #pragma unroll
        for (int ti = 0; ti < 8; ++ti) {
            float e = ex2((sc[ti][tj] - m) * CEXP);
            sc[ti][tj] = e; sum += e;
        }
        sum += __shfl_xor_sync(0xffffffffu, sum, 8);
        sum += __shfl_xor_sync(0xffffffffu, sum, 16);
        float r = 1.0f / sum;
        #pragma unroll
        for (int ti = 0; ti < 8; ++ti) sc[ti][tj] *= r;
    }

    // ---- abar[i] = (1/32) * sum_j a[i][j] ----
    float ab[8];
    #pragma unroll
    for (int ti = 0; ti < 8; ++ti)
        ab[ti] = (sc[ti][0] + sc[ti][1]) + (sc[ti][2] + sc[ti][3]);
    #pragma unroll
    for (int ti = 0; ti < 8; ++ti) {
        ab[ti] += __shfl_xor_sync(0xffffffffu, ab[ti], 1);
        ab[ti] += __shfl_xor_sync(0xffffffffu, ab[ti], 2);
        ab[ti] += __shfl_xor_sync(0xffffffffu, ab[ti], 4);
    }
    if (jg == 0) {
        #pragma unroll
        for (int ti = 0; ti < 8; ++ti)
            ABARw[4 * ti + sg] = ab[ti] * (1.0f / 32.0f);
    }
    __syncwarp();

    // ================= Phase D': om[s] = sum_d v[s][d] * abar[d] ===========
    {
        float4 ab0 = *(const float4*)(ABARw + dgrp * 8);
        float4 ab1 = *(const float4*)(ABARw + dgrp * 8 + 4);
        __syncwarp();
        float abs_[8] = {ab0.x, ab0.y, ab0.z, ab0.w, ab1.x, ab1.y, ab1.z, ab1.w};
        __half2 ao0 = __float2half2_rn(0.f), ao1 = ao0;
        #pragma unroll
        for (int dd = 0; dd < 8; ++dd) {
            __half2 a2 = __float2half2_rn(abs_[dd]);
            ao0 = __hfma2(acV[0][dd], a2, ao0);
            ao1 = __hfma2(acV[1][dd], a2, ao1);
        }
        float o0 = __low2float(ao0), o1 = __high2float(ao0);
        float o2 = __low2float(ao1), o3 = __high2float(ao1);
        o0 += __shfl_xor_sync(0xffffffffu, o0, 1); o0 += __shfl_xor_sync(0xffffffffu, o0, 2);
        o1 += __shfl_xor_sync(0xffffffffu, o1, 1); o1 += __shfl_xor_sync(0xffffffffu, o1, 2);
        o2 += __shfl_xor_sync(0xffffffffu, o2, 1); o2 += __shfl_xor_sync(0xffffffffu, o2, 2);
        o3 += __shfl_xor_sync(0xffffffffu, o3, 1); o3 += __shfl_xor_sync(0xffffffffu, o3, 2);
        if (dgrp == 0) {
            float4 st; st.x = o0; st.y = o1; st.z = o2; st.w = o3;
            *(float4*)(ABARw + sgrp * 4) = st;    // om overwrites abar
        }
    }
    __syncwarp();

    // ================= Phase F: out = mean_d(x) + f*(Wo*om + bo) ===========
    const float fact = factor[0];
    const float mx0 = sm[OFF_MX + warp * CH + lane];
    const float mx1 = sm[OFF_MX + warp * CH + lane + 32];
    float4 om4[8];
    #pragma unroll
    for (int t = 0; t < 8; ++t) om4[t] = *(const float4*)(ABARw + t * 4);
    float ac0 = 0.f, ac1 = 0.f;
    #pragma unroll
    for (int t = 0; t < 8; ++t) {
        const float* wo = sm + OFF_WOT + (4 * t) * CH + lane;
        ac0 += wo[0]   * om4[t].x;  ac1 += wo[32]  * om4[t].x;
        ac0 += wo[64]  * om4[t].y;  ac1 += wo[96]  * om4[t].y;
        ac0 += wo[128] * om4[t].z;  ac1 += wo[160] * om4[t].z;
        ac0 += wo[192] * om4[t].w;  ac1 += wo[224] * om4[t].w;
    }
    float r0 = mx0 * (1.0f / 32.0f) + fact * (ac0 + sm[OFF_BO + lane]);
    float r1 = mx1 * (1.0f / 32.0f) + fact * (ac1 + sm[OFF_BO + lane + 32]);
    sm[OFF_OUT + lane * 8 + warp]        = r0;
    sm[OFF_OUT + (lane + 32) * 8 + warp] = r1;

    __syncthreads();
    // coalesced output: out[b][c][h][w0..w0+7]
    for (int e = tid; e < CH * WT; e += 256) {
        int c = e >> 3, wl = e & 7;
        out[(((size_t)b * CH + c) * H + h) * W + w0 + wl] = sm[OFF_OUT + e];
    }
}

extern "C" void kernel_launch(void* const* d_in, const int* in_sizes, int n_in,
                              void* d_out, int out_size)
{
    (void)in_sizes; (void)n_in; (void)out_size;
    const float* x      = (const float*)d_in[0];
    const float* Wk     = (const float*)d_in[1];
    const float* bk     = (const float*)d_in[2];
    const float* Wq     = (const float*)d_in[3];
    const float* bq     = (const float*)d_in[4];
    const float* Wv     = (const float*)d_in[5];
    const float* bv     = (const float*)d_in[6];
    const float* Wo     = (const float*)d_in[7];
    const float* bo     = (const float*)d_in[8];
    const float* factor = (const float*)d_in[9];
    float* out = (float*)d_out;

    cudaFuncSetAttribute(attn_fused_kernel,
                         cudaFuncAttributeMaxDynamicSharedMemorySize,
                         (int)SMEM_BYTES);
    dim3 grid(B * H * (W / WT));   // 4096
    dim3 block(256);
    attn_fused_kernel<<<grid, block, SMEM_BYTES>>>(
        x, Wk, bk, Wq, bq, Wv, bv, Wo, bo, factor, out);
}